// round 14
// baseline (speedup 1.0000x reference)
#include <cuda_runtime.h>
#include <math.h>
#include <stdint.h>

// ---------------- problem constants ----------------
#define BATCH   4096
#define NBLOCK  100
#define NSLOT   300
#define NYS     1236
#define HIDDIM  256
#define NSTEPS  100
#define KST     1436        // 100 + 100 + 1236
#define M5      (BATCH*5)
#define NFUSE   (NBLOCK+NSLOT) // 400
#define NEGV    (-1000.0f)
#define NCTA    256

typedef unsigned long long ull;

// ---------------- scratch (device globals; no allocs allowed) ----------------
__device__ float g_xT  [(size_t)M5 * KST];
__device__ float g_act1[(size_t)M5 * 512];
__device__ float g_act2[(size_t)M5 * 512];
__device__ float g_act3[(size_t)M5 * 256];
__device__ float g_h_to[2][BATCH*HIDDIM];
__device__ float g_c_to[BATCH*HIDDIM];
__device__ float g_h_ti[2][BATCH*HIDDIM];
__device__ float g_c_ti[BATCH*HIDDIM];
__device__ float g_lto [(size_t)BATCH*NFUSE];
__device__ float g_lti [(size_t)BATCH*NBLOCK];
__device__ float g_inp [BATCH*8];
__device__ unsigned char g_mto[BATCH*NBLOCK];
__device__ unsigned char g_mti[BATCH*NBLOCK];
// SoA slot state (height/location fields are never read after init -> dropped)
__device__ float g_sl0 [(size_t)BATCH*NSLOT];
__device__ float g_sw0 [(size_t)BATCH*NSLOT];
__device__ float g_scnt[(size_t)BATCH*NSLOT];
__device__ float g_WbWs[NFUSE*HIDDIM];
__device__ float g_bf  [NFUSE];
// permuted gate weights: row 4j+g (to: rows 0..1023, ti: rows 1024..2047)
__device__ float g_Wg  [2048*HIDDIM];
__device__ float g_bihp[2048];
__device__ float g_bhhp[2048];
__device__ float g_Wihp[1024*5];
// software global barrier state (gen is monotonic across graph replays)
__device__ unsigned g_barcnt = 0;
__device__ volatile unsigned g_bargen = 0;

// ---------------- packed f32x2 helpers (bitwise == scalar FFMA rn per lane) ----
__device__ __forceinline__ ull ffma2(ull a, ull b, ull c) {
    ull d; asm("fma.rn.f32x2 %0, %1, %2, %3;" : "=l"(d) : "l"(a), "l"(b), "l"(c)); return d;
}
__device__ __forceinline__ ull pack2(float x) {
    ull d; asm("mov.b64 %0, {%1, %1};" : "=l"(d) : "f"(x)); return d;
}
__device__ __forceinline__ void unpack2(ull v, float& lo, float& hi) {
    asm("mov.b64 {%0, %1}, %2;" : "=f"(lo), "=f"(hi) : "l"(v));
}

// ---------------- XLA-GPU-faithful transcendentals ----------------
__device__ __forceinline__ float xla_tanh(float x) {
    float ax = fabsf(x);
    float xc = fminf(fmaxf(x, -7.90531110763549805f), 7.90531110763549805f);
    float x2 = __fmul_rn(xc, xc);
    float p = -2.76076847742355e-16f;
    p = __fadd_rn(__fmul_rn(x2, p),  2.00018790482477e-13f);
    p = __fadd_rn(__fmul_rn(x2, p), -8.60467152213735e-11f);
    p = __fadd_rn(__fmul_rn(x2, p),  5.12229709037114e-08f);
    p = __fadd_rn(__fmul_rn(x2, p),  1.48572235717979e-05f);
    p = __fadd_rn(__fmul_rn(x2, p),  6.37261928875436e-04f);
    p = __fadd_rn(__fmul_rn(x2, p),  4.89352455891786e-03f);
    float num = __fmul_rn(xc, p);
    float q = 1.19825839466702e-06f;
    q = __fadd_rn(__fmul_rn(x2, q), 1.18534705686654e-04f);
    q = __fadd_rn(__fmul_rn(x2, q), 2.26843463243900e-03f);
    q = __fadd_rn(__fmul_rn(x2, q), 4.89352518554385e-03f);
    float r = __fdiv_rn(num, q);
    r = (ax < 0.0004f) ? x : r;
    r = (ax < 20.0f) ? r : copysignf(1.0f, x);
    return r;
}
__device__ __forceinline__ float xla_sigm(float x) {
    return __fdiv_rn(1.0f, __fadd_rn(1.0f, expf(-x)));
}

// ---------------- prep: state copy to output + transposed MLP input ----------------
__global__ void prep_kernel(const float* __restrict__ to_t, const float* __restrict__ ti_t,
                            const float* __restrict__ ys_t, float* __restrict__ out_state)
{
    int idx = blockIdx.x * blockDim.x + threadIdx.x;
    if (idx >= BATCH * KST) return;
    int b = idx / KST, i = idx - b * KST;
    const float* src;
    if (i < NBLOCK)            src = to_t + ((size_t)b * NBLOCK + i) * 5;
    else if (i < 2 * NBLOCK)   src = ti_t + ((size_t)b * NBLOCK + (i - NBLOCK)) * 5;
    else                       src = ys_t + ((size_t)b * NYS + (i - 2 * NBLOCK)) * 5;
#pragma unroll
    for (int r = 0; r < 5; r++) {
        float v = src[r];
        out_state[(size_t)idx * 5 + r] = v;
        g_xT[(size_t)(b * 5 + r) * KST + i] = v;
    }
}

// ---------------- weight prep: permuted gate weights + fused logits weight ------
__global__ void prep_weights(const float* __restrict__ Whh_to, const float* __restrict__ Whh_ti,
                             const float* __restrict__ bih_to, const float* __restrict__ bhh_to,
                             const float* __restrict__ bih_ti, const float* __restrict__ bhh_ti,
                             const float* __restrict__ Wih_to,
                             const float* __restrict__ Wb, const float* __restrict__ bb,
                             const float* __restrict__ Ws, const float* __restrict__ bs)
{
    int r = blockIdx.x, j = threadIdx.x;      // r in 0..2047, j in 0..255
    int rr = r & 1023, g = rr & 3, jj = rr >> 2;
    int src = g * 256 + jj;                   // original gate-major row
    g_Wg[r * 256 + j] = (r < 1024) ? Whh_to[src * 256 + j] : Whh_ti[src * 256 + j];
    if (j == 0) {
        g_bihp[r] = (r < 1024) ? bih_to[src] : bih_ti[src];
        g_bhhp[r] = (r < 1024) ? bhh_to[src] : bhh_ti[src];
    }
    if (r < 1024 && j < 5) g_Wihp[r * 5 + j] = Wih_to[src * 5 + j];
    if (r < NFUSE) {
        g_WbWs[r * 256 + j] = (r < NBLOCK) ? Wb[r * 256 + j] : Ws[(r - NBLOCK) * 256 + j];
        if (j == 0) g_bf[r] = (r < NBLOCK) ? bb[r] : bs[r - NBLOCK];
    }
}

// ---------------- FFMA2 GEMM core (R4, proven) ----------------------------------
#define SMSTRIDE 2112   // 16*132
__device__ __forceinline__ void gemm_core(
    const float* __restrict__ A, int lda,
    const float* __restrict__ Bm, int ldb,
    int m0, int n0, int N, int K,
    float* sA, float* sB, ull acc[8][4])
{
    const int tid = threadIdx.x;
    const int tx = tid & 15, ty = tid >> 4;
#pragma unroll
    for (int i = 0; i < 8; i++)
#pragma unroll
        for (int p = 0; p < 4; p++) acc[i][p] = 0ULL;

    const int T = (K + 15) >> 4;
    const int idx0 = 2 * tid, idx1 = 2 * tid + 1;
    const int ma = idx0 >> 2, kqa = idx0 & 3;
    const int mb = idx1 >> 2, kqb = idx1 & 3;
    const float4 z4 = make_float4(0.f, 0.f, 0.f, 0.f);
    float4 ar0, ar1, br0, br1;
    {
        int gk0 = kqa * 4, gk1 = kqb * 4;
        ar0 = (gk0 < K) ? *(const float4*)(A + (size_t)(m0 + ma) * lda + gk0) : z4;
        ar1 = (gk1 < K) ? *(const float4*)(A + (size_t)(m0 + mb) * lda + gk1) : z4;
        br0 = (gk0 < K && n0 + ma < N) ? *(const float4*)(Bm + (size_t)(n0 + ma) * ldb + gk0) : z4;
        br1 = (gk1 < K && n0 + mb < N) ? *(const float4*)(Bm + (size_t)(n0 + mb) * ldb + gk1) : z4;
        sA[(kqa*4+0)*132+ma]=ar0.x; sA[(kqa*4+1)*132+ma]=ar0.y; sA[(kqa*4+2)*132+ma]=ar0.z; sA[(kqa*4+3)*132+ma]=ar0.w;
        sA[(kqb*4+0)*132+mb]=ar1.x; sA[(kqb*4+1)*132+mb]=ar1.y; sA[(kqb*4+2)*132+mb]=ar1.z; sA[(kqb*4+3)*132+mb]=ar1.w;
        sB[(kqa*4+0)*132+ma]=br0.x; sB[(kqa*4+1)*132+ma]=br0.y; sB[(kqa*4+2)*132+ma]=br0.z; sB[(kqa*4+3)*132+ma]=br0.w;
        sB[(kqb*4+0)*132+mb]=br1.x; sB[(kqb*4+1)*132+mb]=br1.y; sB[(kqb*4+2)*132+mb]=br1.z; sB[(kqb*4+3)*132+mb]=br1.w;
    }
    for (int t = 0; t < T; t++) {
        __syncthreads();
        if (t + 1 < T) {
            int k0 = (t + 1) << 4;
            int gk0 = k0 + kqa * 4, gk1 = k0 + kqb * 4;
            ar0 = (gk0 < K) ? *(const float4*)(A + (size_t)(m0 + ma) * lda + gk0) : z4;
            ar1 = (gk1 < K) ? *(const float4*)(A + (size_t)(m0 + mb) * lda + gk1) : z4;
            br0 = (gk0 < K && n0 + ma < N) ? *(const float4*)(Bm + (size_t)(n0 + ma) * ldb + gk0) : z4;
            br1 = (gk1 < K && n0 + mb < N) ? *(const float4*)(Bm + (size_t)(n0 + mb) * ldb + gk1) : z4;
        }
        const float* pA = sA + (t & 1) * SMSTRIDE;
        const float* pB = sB + (t & 1) * SMSTRIDE;
#pragma unroll
        for (int kk = 0; kk < 16; kk++) {
            const float* rB = pB + kk * 132;
            ull b0 = *(const ull*)(rB + tx * 4);
            ull b1 = *(const ull*)(rB + tx * 4 + 2);
            ull b2 = *(const ull*)(rB + 64 + tx * 4);
            ull b3 = *(const ull*)(rB + 64 + tx * 4 + 2);
            const float* rA = pA + kk * 132;
#pragma unroll
            for (int i = 0; i < 8; i++) {
                float av = (i < 4) ? rA[ty * 4 + i] : rA[64 + ty * 4 + i - 4];
                ull aa = pack2(av);
                acc[i][0] = ffma2(aa, b0, acc[i][0]);
                acc[i][1] = ffma2(aa, b1, acc[i][1]);
                acc[i][2] = ffma2(aa, b2, acc[i][2]);
                acc[i][3] = ffma2(aa, b3, acc[i][3]);
            }
        }
        if (t + 1 < T) {
            float* qA = sA + ((t + 1) & 1) * SMSTRIDE;
            float* qB = sB + ((t + 1) & 1) * SMSTRIDE;
            qA[(kqa*4+0)*132+ma]=ar0.x; qA[(kqa*4+1)*132+ma]=ar0.y; qA[(kqa*4+2)*132+ma]=ar0.z; qA[(kqa*4+3)*132+ma]=ar0.w;
            qA[(kqb*4+0)*132+mb]=ar1.x; qA[(kqb*4+1)*132+mb]=ar1.y; qA[(kqb*4+2)*132+mb]=ar1.z; qA[(kqb*4+3)*132+mb]=ar1.w;
            qB[(kqa*4+0)*132+ma]=br0.x; qB[(kqa*4+1)*132+ma]=br0.y; qB[(kqa*4+2)*132+ma]=br0.z; qB[(kqa*4+3)*132+ma]=br0.w;
            qB[(kqb*4+0)*132+mb]=br1.x; qB[(kqb*4+1)*132+mb]=br1.y; qB[(kqb*4+2)*132+mb]=br1.z; qB[(kqb*4+3)*132+mb]=br1.w;
        }
    }
}
__device__ __forceinline__ int row_of(int i, int m0, int ty) {
    return m0 + ((i < 4) ? (ty * 4 + i) : (64 + ty * 4 + i - 4));
}

// ---------------- plain GEMM kernel (MLP): +bias, relu --------------------------
__global__ void __launch_bounds__(256, 2) sgemm_nt(
    const float* __restrict__ A, int lda,
    const float* __restrict__ Bm, int ldb,
    const float* __restrict__ bias,
    float* __restrict__ C, int ldc,
    int M, int N, int K, int relu)
{
    __shared__ __align__(16) float sA[2 * SMSTRIDE];
    __shared__ __align__(16) float sB[2 * SMSTRIDE];
    ull acc[8][4];
    const int m0 = blockIdx.x * 128, n0 = blockIdx.y * 128;
    gemm_core(A, lda, Bm, ldb, m0, n0, N, K, sA, sB, acc);
    const int tx = threadIdx.x & 15, ty = threadIdx.x >> 4;
#pragma unroll
    for (int i = 0; i < 8; i++) {
        int m = row_of(i, m0, ty);
#pragma unroll
        for (int p = 0; p < 4; p++) {
            float lo, hi; unpack2(acc[i][p], lo, hi);
            int n = n0 + ((p & 2) ? 64 : 0) + tx * 4 + ((p & 1) ? 2 : 0);
            if (n < N) {
                float v = lo;
                if (bias) v = __fadd_rn(v, bias[n]);
                if (relu) v = fmaxf(v, 0.f);
                C[(size_t)m * ldc + n] = v;
            }
            if (n + 1 < N) {
                float v = hi;
                if (bias) v = __fadd_rn(v, bias[n + 1]);
                if (relu) v = fmaxf(v, 0.f);
                C[(size_t)m * ldc + n + 1] = v;
            }
        }
    }
}

// ---------------- LSTM cell helpers (R13-exact) ----------------------------------
__device__ __forceinline__ float dot5_fma(const float* s, const float* w) {
    float a = 0.f;
    a = __fmaf_rn(s[0], w[0], a);
    a = __fmaf_rn(s[1], w[1], a);
    a = __fmaf_rn(s[2], w[2], a);
    a = __fmaf_rn(s[3], w[3], a);
    a = __fmaf_rn(s[4], w[4], a);
    return a;
}

__device__ __forceinline__ void cell_apply(int is_ti, const float gv[4], const float* s5,
                                           const float w[4][5], const float* bi, const float* bh,
                                           float* cptr, float* hptr)
{
    float gt[4];
#pragma unroll
    for (int g = 0; g < 4; g++) {
        float d5 = is_ti ? 0.f : dot5_fma(s5, w[g]);
        gt[g] = __fadd_rn(__fadd_rn(__fadd_rn(d5, bi[g]), gv[g]), bh[g]);
    }
    float cold = *cptr;
    float m1 = __fmul_rn(xla_sigm(gt[1]), cold);
    float m2 = __fmul_rn(xla_sigm(gt[0]), xla_tanh(gt[2]));
    float c  = __fadd_rn(m1, m2);
    *cptr = c;
    *hptr = __fmul_rn(xla_sigm(gt[3]), xla_tanh(c));
}

// ---------------- software global barrier (all NCTA CTAs co-resident) ------------
__device__ __forceinline__ void gbar()
{
    __syncthreads();
    if (threadIdx.x == 0) {
        __threadfence();                       // publish writes + invalidate L1
        unsigned gen = g_bargen;
        if (atomicAdd(&g_barcnt, 1u) == (unsigned)(NCTA - 1)) {
            g_barcnt = 0;
            __threadfence();
            g_bargen = gen + 1;
        } else {
            while (g_bargen == gen) { __nanosleep(64); }
        }
    }
    __syncthreads();
}

// ---------------- persistent scan kernel: 100 steps, 3 phases/step ---------------
__global__ void __launch_bounds__(256, 2) scan_kernel(
    const float* __restrict__ to_t, const float* __restrict__ Wb,
    const float* __restrict__ bb, float* __restrict__ out_act)
{
    __shared__ __align__(16) float sA[2 * SMSTRIDE];
    __shared__ __align__(16) float sB[2 * SMSTRIDE];
    __shared__ float sInp[1024];
    ull acc[8][4];
    const int bid = blockIdx.x;
    const int tid = threadIdx.x;
    const int tx = tid & 15, ty = tid >> 4;
    const int y = bid >> 5, xb = bid & 31;      // gates job coords (y 0..7, xb 0..31)
    const int m0 = xb * 128;

    for (int s = 0; s < NSTEPS; s++) {
        const int cur = s & 1, nxt = cur ^ 1;

        // ================= phase 1: gates GEMM + LSTM cell (to, then ti) ========
#pragma unroll 1
        for (int tensor = 0; tensor < 2; tensor++) {
            __syncthreads();
            const float* A = tensor ? g_h_ti[cur] : g_h_to[cur];
            const int n0 = tensor * 1024 + y * 128;
            gemm_core(A, HIDDIM, g_Wg, HIDDIM, m0, n0, 2048, HIDDIM, sA, sB, acc);
            __syncthreads();
            if (!tensor) {
                for (int idx = tid; idx < 1024; idx += 256) sInp[idx] = g_inp[m0 * 8 + idx];
                __syncthreads();
            }

            const int jA = y * 32 + tx;
            const int jB = jA + 16;
            const int nA = n0 + tx * 4;
            const int nB = n0 + 64 + tx * 4;

            float biA[4], bhA[4], biB[4], bhB[4];
#pragma unroll
            for (int g = 0; g < 4; g++) {
                biA[g] = g_bihp[nA + g]; bhA[g] = g_bhhp[nA + g];
                biB[g] = g_bihp[nB + g]; bhB[g] = g_bhhp[nB + g];
            }
            float wA[4][5], wB[4][5];
            if (!tensor) {
#pragma unroll
                for (int g = 0; g < 4; g++)
#pragma unroll
                    for (int r = 0; r < 5; r++) {
                        wA[g][r] = g_Wihp[(nA + g) * 5 + r];
                        wB[g][r] = g_Wihp[(nB + g) * 5 + r];
                    }
            }
            float* cbuf = tensor ? g_c_ti : g_c_to;
            float* hn   = tensor ? g_h_ti[nxt] : g_h_to[nxt];

#pragma unroll
            for (int i = 0; i < 8; i++) {
                int mloc = (i < 4) ? (ty * 4 + i) : (64 + ty * 4 + i - 4);
                int m = m0 + mloc;
                float s5[5];
                if (!tensor) {
#pragma unroll
                    for (int r = 0; r < 5; r++) s5[r] = sInp[mloc * 8 + r];
                }
                float ga[4], gb[4];
                unpack2(acc[i][0], ga[0], ga[1]); unpack2(acc[i][1], ga[2], ga[3]);
                unpack2(acc[i][2], gb[0], gb[1]); unpack2(acc[i][3], gb[2], gb[3]);
                cell_apply(tensor, ga, s5, wA, biA, bhA, cbuf + (size_t)m * HIDDIM + jA, hn + (size_t)m * HIDDIM + jA);
                cell_apply(tensor, gb, s5, wB, biB, bhB, cbuf + (size_t)m * HIDDIM + jB, hn + (size_t)m * HIDDIM + jB);
            }
        }
        gbar();

        // ================= phase 2: logits GEMM (160 CTAs work) =================
        if (bid < 160) {
            const int ly = bid >> 5, lxb = bid & 31;
            const float *A, *B, *bias; float* C; int N, ldc, ln0;
            if (ly < 4) { A = g_h_to[nxt]; B = g_WbWs; bias = g_bf; C = g_lto; N = NFUSE; ldc = NFUSE; ln0 = ly * 128; }
            else        { A = g_h_ti[nxt]; B = Wb;     bias = bb;   C = g_lti; N = NBLOCK; ldc = NBLOCK; ln0 = 0; }
            const int lm0 = lxb * 128;
            __syncthreads();
            gemm_core(A, HIDDIM, B, HIDDIM, lm0, ln0, N, HIDDIM, sA, sB, acc);
#pragma unroll
            for (int i = 0; i < 8; i++) {
                int m = row_of(i, lm0, ty);
#pragma unroll
                for (int p = 0; p < 4; p++) {
                    float lo, hi; unpack2(acc[i][p], lo, hi);
                    int n = ln0 + ((p & 2) ? 64 : 0) + tx * 4 + ((p & 1) ? 2 : 0);
                    if (n < N)     C[(size_t)m * ldc + n]     = __fadd_rn(lo, bias[n]);
                    if (n + 1 < N) C[(size_t)m * ldc + n + 1] = __fadd_rn(hi, bias[n + 1]);
                }
            }
        }
        gbar();

        // ================= phase 3: select (16 batches per CTA) =================
        {
            const int w = tid >> 5, l = tid & 31;
#pragma unroll 1
            for (int bb2 = 0; bb2 < 2; bb2++) {
                const int b = bid * 16 + w * 2 + bb2;

                // ---- block argmax (h_to logits) ----
                float v = -3.4e38f; int bi = 0x7fffffff;
                for (int i = l; i < NBLOCK; i += 32) {
                    float lv = g_mto[b * NBLOCK + i] ? g_lto[(size_t)b * NFUSE + i] : NEGV;
                    if (lv > v || (lv == v && i < bi)) { v = lv; bi = i; }
                }
#pragma unroll
                for (int o = 16; o; o >>= 1) {
                    float v2 = __shfl_xor_sync(0xffffffffu, v, o);
                    int   i2 = __shfl_xor_sync(0xffffffffu, bi, o);
                    if (v2 > v || (v2 == v && i2 < bi)) { v = v2; bi = i2; }
                }
                const int sel_b = bi;
                if (l == 0) {
                    g_mto[b * NBLOCK + sel_b] = 0;
#pragma unroll
                    for (int r = 0; r < 5; r++)
                        g_inp[b * 8 + r] = to_t[((size_t)b * NBLOCK + sel_b) * 5 + r];
                }
                const float bl0 = to_t[((size_t)b * NBLOCK + sel_b) * 5 + 0];
                const float bl1 = to_t[((size_t)b * NBLOCK + sel_b) * 5 + 1];

                // ---- slot argmax (SoA) ----
                v = -3.4e38f; bi = 0x7fffffff;
                for (int i = l; i < NSLOT; i += 32) {
                    float l0 = g_sl0[(size_t)b * NSLOT + i];
                    float w0 = g_sw0[(size_t)b * NSLOT + i];
                    bool bad = (bl0 >= l0) || (bl1 >= w0) || (l0 == 0.0f);
                    float lv = bad ? NEGV : g_lto[(size_t)b * NFUSE + NBLOCK + i];
                    if (lv > v || (lv == v && i < bi)) { v = lv; bi = i; }
                }
#pragma unroll
                for (int o = 16; o; o >>= 1) {
                    float v2 = __shfl_xor_sync(0xffffffffu, v, o);
                    int   i2 = __shfl_xor_sync(0xffffffffu, bi, o);
                    if (v2 > v || (v2 == v && i2 < bi)) { v = v2; bi = i2; }
                }
                const int sel_s = bi;
                if (l == 0) {
                    size_t si = (size_t)b * NSLOT + sel_s;
                    float cnt = __fadd_rn(g_scnt[si], -1.0f);
                    g_scnt[si] = cnt;
                    if (cnt == 0.0f) { g_sl0[si] = 0.f; g_sw0[si] = 0.f; }
                }

                // ---- ti block argmax (h_ti logits) ----
                v = -3.4e38f; bi = 0x7fffffff;
                for (int i = l; i < NBLOCK; i += 32) {
                    float lv = g_mti[b * NBLOCK + i] ? g_lti[(size_t)b * NBLOCK + i] : NEGV;
                    if (lv > v || (lv == v && i < bi)) { v = lv; bi = i; }
                }
#pragma unroll
                for (int o = 16; o; o >>= 1) {
                    float v2 = __shfl_xor_sync(0xffffffffu, v, o);
                    int   i2 = __shfl_xor_sync(0xffffffffu, bi, o);
                    if (v2 > v || (v2 == v && i2 < bi)) { v = v2; bi = i2; }
                }
                if (l == 0) {
                    g_mti[b * NBLOCK + bi] = 0;
                    float* oa = out_act + ((size_t)b * NSTEPS + s) * 3;
                    oa[0] = (float)sel_b;
                    oa[1] = (float)sel_s;
                    oa[2] = (float)bi;
                }
            }
        }
        gbar();
    }
}

// ---------------- feat_vec + carry init ----------------
__global__ void feat_init_kernel(const float* __restrict__ W_fe2, const float* __restrict__ b_fe2,
                                 const float* __restrict__ to_t, const float* __restrict__ ti_t,
                                 const float* __restrict__ slot_info)
{
    int b = blockIdx.x, j = threadIdx.x;
    float f = 0.f;
#pragma unroll
    for (int r = 0; r < 5; r++)
        f = __fmaf_rn(g_act3[(size_t)(b * 5 + r) * HIDDIM + j], W_fe2[r], f);
    f = __fadd_rn(f, b_fe2[0]);
    g_h_to[0][b * HIDDIM + j] = f;
    g_h_ti[0][b * HIDDIM + j] = f;
    g_c_to[b * HIDDIM + j] = 0.f;
    g_c_ti[b * HIDDIM + j] = 0.f;
    if (j < 8) g_inp[b * 8 + j] = 0.f;
    if (j < NBLOCK) {
        g_mto[b * NBLOCK + j] = (to_t[((size_t)b * NBLOCK + j) * 5] != -1.0f);
        g_mti[b * NBLOCK + j] = (ti_t[((size_t)b * NBLOCK + j) * 5] != -1.0f);
    }
    for (int i = j; i < NSLOT; i += HIDDIM) {
        const float* sl = slot_info + ((size_t)b * NSLOT + i) * 5;
        g_sl0 [(size_t)b * NSLOT + i] = sl[0];
        g_sw0 [(size_t)b * NSLOT + i] = sl[1];
        g_scnt[(size_t)b * NSLOT + i] = sl[4];
    }
}

// ---------------- launch ----------------
extern "C" void kernel_launch(void* const* d_in, const int* in_sizes, int n_in,
                              void* d_out, int out_size)
{
    const float* to_t    = (const float*)d_in[0];
    const float* ti_t    = (const float*)d_in[1];
    const float* ys_t    = (const float*)d_in[2];
    const float* slot    = (const float*)d_in[3];
    const float* W1      = (const float*)d_in[4];
    const float* b1      = (const float*)d_in[5];
    const float* W2      = (const float*)d_in[6];
    const float* b2      = (const float*)d_in[7];
    const float* W3      = (const float*)d_in[8];
    const float* b3      = (const float*)d_in[9];
    const float* W_fe2   = (const float*)d_in[10];
    const float* b_fe2   = (const float*)d_in[11];
    const float* Wih_to  = (const float*)d_in[12];
    const float* Whh_to  = (const float*)d_in[13];
    const float* bih_to  = (const float*)d_in[14];
    const float* bhh_to  = (const float*)d_in[15];
    const float* Whh_ti  = (const float*)d_in[17];
    const float* bih_ti  = (const float*)d_in[18];
    const float* bhh_ti  = (const float*)d_in[19];
    const float* Wb      = (const float*)d_in[20];
    const float* bb      = (const float*)d_in[21];
    const float* Ws      = (const float*)d_in[22];
    const float* bs      = (const float*)d_in[23];

    float* out     = (float*)d_out;
    float* out_act = out + (size_t)BATCH * KST * 5;

    float *p_xT, *p_a1, *p_a2, *p_a3;
    cudaGetSymbolAddress((void**)&p_xT,  g_xT);
    cudaGetSymbolAddress((void**)&p_a1,  g_act1);
    cudaGetSymbolAddress((void**)&p_a2,  g_act2);
    cudaGetSymbolAddress((void**)&p_a3,  g_act3);

    // prep
    int nprep = (BATCH * KST + 255) / 256;
    prep_kernel<<<nprep, 256>>>(to_t, ti_t, ys_t, out);
    prep_weights<<<2048, 256>>>(Whh_to, Whh_ti, bih_to, bhh_to, bih_ti, bhh_ti,
                                Wih_to, Wb, bb, Ws, bs);

    // MLP
    dim3 g1(M5 / 128, 512 / 128);
    sgemm_nt<<<g1, 256>>>(p_xT, KST, W1, KST, b1, p_a1, 512, M5, 512, KST, 1);
    sgemm_nt<<<g1, 256>>>(p_a1, 512, W2, 512, b2, p_a2, 512, M5, 512, 512, 1);
    dim3 g3(M5 / 128, 256 / 128);
    sgemm_nt<<<g3, 256>>>(p_a2, 512, W3, 512, b3, p_a3, 256, M5, 256, 512, 1);
    feat_init_kernel<<<BATCH, HIDDIM>>>(W_fe2, b_fe2, to_t, ti_t, slot);

    // persistent 100-step scan: one launch, software global barriers
    scan_kernel<<<NCTA, 256>>>(to_t, Wb, bb, out_act);
}